// round 1
// baseline (speedup 1.0000x reference)
#include <cuda_runtime.h>

// Problem constants (fixed shapes for this problem instance)
#define NN 50000
#define EE 800000
#define DD 128
#define HH 256
#define GG 512
#define LL 3
#define BN_EPS 1e-5f

// ---------------- scratch (static device globals; no allocation) -------------
__device__ float g_hin[NN * DD];
__device__ float g_aggr[NN * DD];
__device__ float g_h[NN * DD];
__device__ float g_z1[NN * HH];
__device__ float g_z2[NN * DD];
__device__ float g_vn[GG * DD];
__device__ float g_pooled[GG * DD];
__device__ float g_tv1[GG * HH];
__device__ float g_tv2[GG * DD];
__device__ float g_sum[HH];
__device__ float g_sumsq[HH];
__device__ float g_scale[HH];
__device__ float g_shift[HH];

// ---------------- helpers ----------------------------------------------------
__device__ __forceinline__ void atomic_add_f4(float* addr, float4 v) {
    asm volatile("red.global.add.v4.f32 [%0], {%1,%2,%3,%4};"
                 :: "l"(addr), "f"(v.x), "f"(v.y), "f"(v.z), "f"(v.w)
                 : "memory");
}

__global__ void zero_kernel(float* __restrict__ p, int n4) {
    int idx = blockIdx.x * blockDim.x + threadIdx.x;
    int stride = gridDim.x * blockDim.x;
    float4 z = make_float4(0.f, 0.f, 0.f, 0.f);
    for (int i = idx; i < n4; i += stride)
        reinterpret_cast<float4*>(p)[i] = z;
}

__global__ void zero_stats_kernel(float* __restrict__ s, float* __restrict__ q) {
    int t = threadIdx.x;
    if (t < HH) { s[t] = 0.f; q[t] = 0.f; }
}

// vn[g][j] = vn_emb[j]
__global__ void init_vn_kernel(const float* __restrict__ vn_emb, float* __restrict__ vn) {
    int idx = blockIdx.x * blockDim.x + threadIdx.x;
    if (idx < GG * DD) vn[idx] = vn_emb[idx & (DD - 1)];
}

// h_in = h + vn[batch]
__global__ void hin_kernel(const float* __restrict__ h, const float* __restrict__ vn,
                           const int* __restrict__ batch, float* __restrict__ hin, int n) {
    int idx = blockIdx.x * blockDim.x + threadIdx.x;   // one float4 each
    int total = n * (DD / 4);
    if (idx >= total) return;
    int row = idx >> 5;            // DD/4 = 32
    int c4 = (idx & 31) << 2;
    int g = batch[row];
    const float4 a = *reinterpret_cast<const float4*>(h + (size_t)row * DD + c4);
    const float4 b = *reinterpret_cast<const float4*>(vn + (size_t)g * DD + c4);
    float4 o = make_float4(a.x + b.x, a.y + b.y, a.z + b.z, a.w + b.w);
    *reinterpret_cast<float4*>(hin + (size_t)row * DD + c4) = o;
}

// pooled[batch[i]] += h_in[i]
__global__ void pool_kernel(const float* __restrict__ hin, const int* __restrict__ batch,
                            float* __restrict__ pooled, int n) {
    int idx = blockIdx.x * blockDim.x + threadIdx.x;
    int total = n * (DD / 4);
    if (idx >= total) return;
    int row = idx >> 5;
    int c4 = (idx & 31) << 2;
    int g = batch[row];
    const float4 v = *reinterpret_cast<const float4*>(hin + (size_t)row * DD + c4);
    atomic_add_f4(pooled + (size_t)g * DD + c4, v);
}

// Per-edge: e = edge_attr @ We + be ; msg = relu(h_in[src] + e) ; aggr[dst] += msg
// one warp per edge, lane handles 4 feature columns (float4)
__global__ void __launch_bounds__(256) edge_kernel(
    const float* __restrict__ ea, const float* __restrict__ We, const float* __restrict__ be,
    const float* __restrict__ hin, const int* __restrict__ src, const int* __restrict__ dst,
    float* __restrict__ aggr, int E)
{
    int lane = threadIdx.x & 31;
    int warp = (blockIdx.x * blockDim.x + threadIdx.x) >> 5;
    int nwarps = (gridDim.x * blockDim.x) >> 5;

    // per-lane weight columns (each lane owns cols lane*4 .. lane*4+3)
    float4 w[8];
#pragma unroll
    for (int k = 0; k < 8; k++)
        w[k] = __ldg(reinterpret_cast<const float4*>(We + k * DD + lane * 4));
    const float4 bb = __ldg(reinterpret_cast<const float4*>(be + lane * 4));

    for (int e = warp; e < E; e += nwarps) {
        const float4 a0 = __ldg(reinterpret_cast<const float4*>(ea + (size_t)e * 8));
        const float4 a1 = __ldg(reinterpret_cast<const float4*>(ea + (size_t)e * 8 + 4));
        int s = __ldg(src + e);
        int d = __ldg(dst + e);
        float ak[8] = {a0.x, a0.y, a0.z, a0.w, a1.x, a1.y, a1.z, a1.w};
        float4 ev = bb;
#pragma unroll
        for (int k = 0; k < 8; k++) {
            ev.x = fmaf(ak[k], w[k].x, ev.x);
            ev.y = fmaf(ak[k], w[k].y, ev.y);
            ev.z = fmaf(ak[k], w[k].z, ev.z);
            ev.w = fmaf(ak[k], w[k].w, ev.w);
        }
        const float4 hv = __ldg(reinterpret_cast<const float4*>(hin + (size_t)s * DD + lane * 4));
        float4 m;
        m.x = fmaxf(hv.x + ev.x, 0.f);
        m.y = fmaxf(hv.y + ev.y, 0.f);
        m.z = fmaxf(hv.z + ev.z, 0.f);
        m.w = fmaxf(hv.w + ev.w, 0.f);
        atomic_add_f4(aggr + (size_t)d * DD + lane * 4, m);
    }
}

// ------------------ tiled SGEMM: C[MxF] = op(A)[MxK] @ B[KxF] + bias ----------
// MODE 0: A = A1 + A2  (elementwise, both MxK)
// MODE 1: A = relu(scale[k]*A1 + shift[k])  (fused BN+relu on input features)
template <int MODE>
__global__ void __launch_bounds__(256) gemm_kernel(
    const float* __restrict__ A1, const float* __restrict__ A2,
    const float* __restrict__ bnscale, const float* __restrict__ bnshift,
    const float* __restrict__ B, const float* __restrict__ bias,
    float* __restrict__ C, int M, int K, int F)
{
    const int BM = 128, BN = 128, BK = 16;
    __shared__ float sA[BK][BM];
    __shared__ float sB[BK][BN];
    int tid = threadIdx.x;
    int brow = blockIdx.y * BM;
    int bcol = blockIdx.x * BN;

    float acc[8][8];
#pragma unroll
    for (int i = 0; i < 8; i++)
#pragma unroll
        for (int j = 0; j < 8; j++) acc[i][j] = 0.f;

    int tr = (tid >> 4) << 3;
    int tc = (tid & 15) << 3;

    for (int k0 = 0; k0 < K; k0 += BK) {
        // ---- load A tile (BM x BK), transposed into sA ----
#pragma unroll
        for (int i = 0; i < 2; i++) {
            int idx = tid + i * 256;
            int r = idx >> 2;
            int c4 = (idx & 3) << 2;
            int row = brow + r;
            float4 v = make_float4(0.f, 0.f, 0.f, 0.f);
            if (row < M) {
                size_t off = (size_t)row * K + k0 + c4;
                if (MODE == 0) {
                    float4 a = __ldg(reinterpret_cast<const float4*>(A1 + off));
                    float4 b = __ldg(reinterpret_cast<const float4*>(A2 + off));
                    v = make_float4(a.x + b.x, a.y + b.y, a.z + b.z, a.w + b.w);
                } else {
                    float4 a = __ldg(reinterpret_cast<const float4*>(A1 + off));
                    float4 s = __ldg(reinterpret_cast<const float4*>(bnscale + k0 + c4));
                    float4 t = __ldg(reinterpret_cast<const float4*>(bnshift + k0 + c4));
                    v.x = fmaxf(fmaf(s.x, a.x, t.x), 0.f);
                    v.y = fmaxf(fmaf(s.y, a.y, t.y), 0.f);
                    v.z = fmaxf(fmaf(s.z, a.z, t.z), 0.f);
                    v.w = fmaxf(fmaf(s.w, a.w, t.w), 0.f);
                }
            }
            sA[c4 + 0][r] = v.x;
            sA[c4 + 1][r] = v.y;
            sA[c4 + 2][r] = v.z;
            sA[c4 + 3][r] = v.w;
        }
        // ---- load B tile (BK x BN) ----
#pragma unroll
        for (int i = 0; i < 2; i++) {
            int idx = tid + i * 256;
            int r = idx >> 5;
            int c4 = (idx & 31) << 2;
            float4 v = __ldg(reinterpret_cast<const float4*>(B + (size_t)(k0 + r) * F + bcol + c4));
            *reinterpret_cast<float4*>(&sB[r][c4]) = v;
        }
        __syncthreads();
#pragma unroll
        for (int kk = 0; kk < BK; kk++) {
            float a[8], b[8];
            *reinterpret_cast<float4*>(&a[0]) = *reinterpret_cast<float4*>(&sA[kk][tr]);
            *reinterpret_cast<float4*>(&a[4]) = *reinterpret_cast<float4*>(&sA[kk][tr + 4]);
            *reinterpret_cast<float4*>(&b[0]) = *reinterpret_cast<float4*>(&sB[kk][tc]);
            *reinterpret_cast<float4*>(&b[4]) = *reinterpret_cast<float4*>(&sB[kk][tc + 4]);
#pragma unroll
            for (int i = 0; i < 8; i++)
#pragma unroll
                for (int j = 0; j < 8; j++)
                    acc[i][j] = fmaf(a[i], b[j], acc[i][j]);
        }
        __syncthreads();
    }
    // ---- epilogue: + bias, store raw ----
#pragma unroll
    for (int i = 0; i < 8; i++) {
        int row = brow + tr + i;
        if (row < M) {
#pragma unroll
            for (int j = 0; j < 8; j += 4) {
                float4 bv = __ldg(reinterpret_cast<const float4*>(bias + bcol + tc + j));
                float4 o;
                o.x = acc[i][j + 0] + bv.x;
                o.y = acc[i][j + 1] + bv.y;
                o.z = acc[i][j + 2] + bv.z;
                o.w = acc[i][j + 3] + bv.w;
                *reinterpret_cast<float4*>(C + (size_t)row * F + bcol + tc + j) = o;
            }
        }
    }
}

// column sums / sums of squares; blockDim.x must equal F
__global__ void stats_kernel(const float* __restrict__ Z, int M, int F,
                             float* __restrict__ gsum, float* __restrict__ gsq) {
    int col = threadIdx.x;
    int r0 = blockIdx.x * 128;
    int rend = min(r0 + 128, M);
    float s = 0.f, q = 0.f;
    for (int r = r0; r < rend; r++) {
        float v = Z[(size_t)r * F + col];
        s += v;
        q = fmaf(v, v, q);
    }
    atomicAdd(&gsum[col], s);
    atomicAdd(&gsq[col], q);
}

// scale = gamma*rsqrt(var+eps); shift = beta - mean*scale; blockDim.x == F
__global__ void bn_finalize_kernel(const float* __restrict__ gsum, const float* __restrict__ gsq,
                                   const float* __restrict__ gamma, const float* __restrict__ beta,
                                   int M, float* __restrict__ scale, float* __restrict__ shift) {
    int f = threadIdx.x;
    float invM = 1.f / (float)M;
    float mean = gsum[f] * invM;
    float var = gsq[f] * invM - mean * mean;
    float inv = rsqrtf(var + BN_EPS);
    float sc = gamma[f] * inv;
    scale[f] = sc;
    shift[f] = beta[f] - mean * sc;
}

// out = (relu?)(scale*Z + shift), elementwise; F is 128 or 256
__global__ void bn_apply_kernel(const float* __restrict__ Z, const float* __restrict__ scale,
                                const float* __restrict__ shift, float* __restrict__ out,
                                int M, int F, int do_relu) {
    int idx = blockIdx.x * blockDim.x + threadIdx.x;  // one float4 each
    int total = M * (F >> 2);
    if (idx >= total) return;
    int cols4 = F >> 2;
    int row = idx / cols4;
    int c4 = (idx - row * cols4) << 2;
    float4 z = *reinterpret_cast<const float4*>(Z + (size_t)row * F + c4);
    float4 s = __ldg(reinterpret_cast<const float4*>(scale + c4));
    float4 t = __ldg(reinterpret_cast<const float4*>(shift + c4));
    float4 o;
    o.x = fmaf(s.x, z.x, t.x);
    o.y = fmaf(s.y, z.y, t.y);
    o.z = fmaf(s.z, z.z, t.z);
    o.w = fmaf(s.w, z.w, t.w);
    if (do_relu) {
        o.x = fmaxf(o.x, 0.f);
        o.y = fmaxf(o.y, 0.f);
        o.z = fmaxf(o.z, 0.f);
        o.w = fmaxf(o.w, 0.f);
    }
    *reinterpret_cast<float4*>(out + (size_t)row * F + c4) = o;
}

// ------------------------------ host driver ----------------------------------
static inline int cdiv(int a, int b) { return (a + b - 1) / b; }

extern "C" void kernel_launch(void* const* d_in, const int* in_sizes, int n_in,
                              void* d_out, int out_size) {
    const float* x        = (const float*)d_in[0];
    const float* edge_attr= (const float*)d_in[1];
    const float* vn_emb   = (const float*)d_in[2];
    const float* We   = (const float*)d_in[3];
    const float* be   = (const float*)d_in[4];
    const float* W1   = (const float*)d_in[5];
    const float* b1   = (const float*)d_in[6];
    const float* g1   = (const float*)d_in[7];
    const float* bt1  = (const float*)d_in[8];
    const float* W2   = (const float*)d_in[9];
    const float* b2   = (const float*)d_in[10];
    const float* gb   = (const float*)d_in[11];
    const float* bbp  = (const float*)d_in[12];
    const float* Wv1  = (const float*)d_in[13];
    const float* bv1  = (const float*)d_in[14];
    const float* gv1  = (const float*)d_in[15];
    const float* btv1 = (const float*)d_in[16];
    const float* Wv2  = (const float*)d_in[17];
    const float* bv2  = (const float*)d_in[18];
    const float* gv2  = (const float*)d_in[19];
    const float* btv2 = (const float*)d_in[20];
    const int* edge_index = (const int*)d_in[21];
    const int* batch      = (const int*)d_in[22];

    const int N = in_sizes[0] / DD;
    const int E = in_sizes[1] / 8;
    const int* srcp = edge_index;
    const int* dstp = edge_index + E;
    float* out = (float*)d_out;

    float *p_hin, *p_aggr, *p_h, *p_z1, *p_z2, *p_vn, *p_pooled, *p_tv1, *p_tv2;
    float *p_sum, *p_sq, *p_scale, *p_shift;
    cudaGetSymbolAddress((void**)&p_hin, g_hin);
    cudaGetSymbolAddress((void**)&p_aggr, g_aggr);
    cudaGetSymbolAddress((void**)&p_h, g_h);
    cudaGetSymbolAddress((void**)&p_z1, g_z1);
    cudaGetSymbolAddress((void**)&p_z2, g_z2);
    cudaGetSymbolAddress((void**)&p_vn, g_vn);
    cudaGetSymbolAddress((void**)&p_pooled, g_pooled);
    cudaGetSymbolAddress((void**)&p_tv1, g_tv1);
    cudaGetSymbolAddress((void**)&p_tv2, g_tv2);
    cudaGetSymbolAddress((void**)&p_sum, g_sum);
    cudaGetSymbolAddress((void**)&p_sq, g_sumsq);
    cudaGetSymbolAddress((void**)&p_scale, g_scale);
    cudaGetSymbolAddress((void**)&p_shift, g_shift);

    // init virtual node
    init_vn_kernel<<<cdiv(GG * DD, 256), 256>>>(vn_emb, p_vn);

    const float* hcur = x;
    const int nf4 = N * (DD / 4);

    for (int l = 0; l < LL; l++) {
        // aggr = 0
        zero_kernel<<<cdiv(N * DD / 4, 256), 256>>>(p_aggr, N * DD / 4);
        // h_in = h + vn[batch]
        hin_kernel<<<cdiv(nf4, 256), 256>>>(hcur, p_vn, batch, p_hin, N);
        // edge messages + scatter
        edge_kernel<<<2048, 256>>>(edge_attr, We + (size_t)l * 8 * DD, be + (size_t)l * DD,
                                   p_hin, srcp, dstp, p_aggr, E);
        // z1 = (h_in + aggr) @ W1 + b1   [N x HH]
        {
            dim3 grid(HH / 128, cdiv(N, 128));
            gemm_kernel<0><<<grid, 256>>>(p_hin, p_aggr, nullptr, nullptr,
                                          W1 + (size_t)l * DD * HH, b1 + (size_t)l * HH,
                                          p_z1, N, DD, HH);
        }
        zero_stats_kernel<<<1, HH>>>(p_sum, p_sq);
        stats_kernel<<<cdiv(N, 128), HH>>>(p_z1, N, HH, p_sum, p_sq);
        bn_finalize_kernel<<<1, HH>>>(p_sum, p_sq, g1 + (size_t)l * HH, bt1 + (size_t)l * HH,
                                      N, p_scale, p_shift);
        // z2 = relu(BN(z1)) @ W2 + b2    [N x DD]
        {
            dim3 grid(DD / 128, cdiv(N, 128));
            gemm_kernel<1><<<grid, 256>>>(p_z1, nullptr, p_scale, p_shift,
                                          W2 + (size_t)l * HH * DD, b2 + (size_t)l * DD,
                                          p_z2, N, HH, DD);
        }
        zero_stats_kernel<<<1, HH>>>(p_sum, p_sq);
        stats_kernel<<<cdiv(N, 128), DD>>>(p_z2, N, DD, p_sum, p_sq);
        bn_finalize_kernel<<<1, DD>>>(p_sum, p_sq, gb + (size_t)l * DD, bbp + (size_t)l * DD,
                                      N, p_scale, p_shift);

        if (l < LL - 1) {
            // h = relu(BN(z2))
            bn_apply_kernel<<<cdiv(nf4, 256), 256>>>(p_z2, p_scale, p_shift, p_h, N, DD, 1);
            // ---- virtual node update ----
            zero_kernel<<<cdiv(GG * DD / 4, 256), 256>>>(p_pooled, GG * DD / 4);
            pool_kernel<<<cdiv(nf4, 256), 256>>>(p_hin, batch, p_pooled, N);
            {
                dim3 grid(HH / 128, cdiv(GG, 128));
                gemm_kernel<0><<<grid, 256>>>(p_pooled, p_vn, nullptr, nullptr,
                                              Wv1 + (size_t)l * DD * HH, bv1 + (size_t)l * HH,
                                              p_tv1, GG, DD, HH);
            }
            zero_stats_kernel<<<1, HH>>>(p_sum, p_sq);
            stats_kernel<<<cdiv(GG, 128), HH>>>(p_tv1, GG, HH, p_sum, p_sq);
            bn_finalize_kernel<<<1, HH>>>(p_sum, p_sq, gv1 + (size_t)l * HH, btv1 + (size_t)l * HH,
                                          GG, p_scale, p_shift);
            {
                dim3 grid(DD / 128, cdiv(GG, 128));
                gemm_kernel<1><<<grid, 256>>>(p_tv1, nullptr, p_scale, p_shift,
                                              Wv2 + (size_t)l * HH * DD, bv2 + (size_t)l * DD,
                                              p_tv2, GG, HH, DD);
            }
            zero_stats_kernel<<<1, HH>>>(p_sum, p_sq);
            stats_kernel<<<cdiv(GG, 128), DD>>>(p_tv2, GG, DD, p_sum, p_sq);
            bn_finalize_kernel<<<1, DD>>>(p_sum, p_sq, gv2 + (size_t)l * DD, btv2 + (size_t)l * DD,
                                          GG, p_scale, p_shift);
            bn_apply_kernel<<<cdiv(GG * DD / 4, 256), 256>>>(p_tv2, p_scale, p_shift, p_vn, GG, DD, 1);

            hcur = p_h;
        } else {
            // final layer: h = BN(z2), no relu, straight to output
            bn_apply_kernel<<<cdiv(nf4, 256), 256>>>(p_z2, p_scale, p_shift, out, N, DD, 0);
        }
    }
}